// round 5
// baseline (speedup 1.0000x reference)
#include <cuda_runtime.h>
#include <math.h>

#define B 16
#define L 128
#define H 1024
#define V 50257
#define T (L-1)
#define BP (B/2)

typedef unsigned long long u64;

// ---- scratch (no allocations allowed) ----
__device__ float g_x0[B * H];
__device__ float g_h0[B * H];
__device__ float g_h0p[4][B * H];
__device__ float g_gi[B * 3 * H];
__device__ float g_gh[B * 3 * H];
__device__ float g_h1[B * H];
__device__ float g_logits[(size_t)B * V];
__device__ float g_m[B];
__device__ float g_l[B];

// packed f32x2 FMA: d = a*b + d (2 MACs / SASS instr)
__device__ __forceinline__ void ffma2(u64 &d, u64 a, u64 b) {
    asm("fma.rn.f32x2 %0, %1, %2, %0;" : "+l"(d) : "l"(a), "l"(b));
}
// duplicate scalar into both halves of a pack
__device__ __forceinline__ u64 dup2(float f) {
    u64 r;
    asm("mov.b64 %0, {%1, %1};" : "=l"(r) : "f"(f));
    return r;
}
__device__ __forceinline__ float lo2(u64 a) { return __uint_as_float((unsigned)a); }
__device__ __forceinline__ float hi2(u64 a) { return __uint_as_float((unsigned)(a >> 32)); }

// ---------------------------------------------------------------------------
// K1a: partial bridge reduction. grid=(64,4); chunk c covers l in [32c,32c+32)
// ---------------------------------------------------------------------------
__global__ void k1a_bridge_part(const float* __restrict__ hidden,
                                const float* __restrict__ bridge_w) {
    __shared__ float bw[32];
    int c = blockIdx.y;
    if (threadIdx.x < 32) bw[threadIdx.x] = bridge_w[c * 32 + threadIdx.x];
    __syncthreads();

    int i = blockIdx.x * 256 + threadIdx.x;
    int b = i >> 10;
    int h = i & (H - 1);
    const float* hp = hidden + (size_t)b * L * H + (size_t)(c * 32) * H + h;
    float a0 = 0.f, a1 = 0.f, a2 = 0.f, a3 = 0.f;
    #pragma unroll
    for (int l = 0; l < 32; l += 4) {
        a0 += hp[(l + 0) * H] * bw[l + 0];
        a1 += hp[(l + 1) * H] * bw[l + 1];
        a2 += hp[(l + 2) * H] * bw[l + 2];
        a3 += hp[(l + 3) * H] * bw[l + 3];
    }
    g_h0p[c][i] = (a0 + a1) + (a2 + a3);
}

// ---------------------------------------------------------------------------
// K1b: combine partials + bias; x0 = relu(emb[input[:,0]])
// ---------------------------------------------------------------------------
__global__ void k1b_combine(const int* __restrict__ input,
                            const float* __restrict__ emb,
                            const float* __restrict__ bridge_b) {
    int i = blockIdx.x * 256 + threadIdx.x;
    int b = i >> 10;
    int h = i & (H - 1);
    int tok = input[b * L];
    g_x0[i] = fmaxf(emb[(size_t)tok * H + h], 0.0f);
    g_h0[i] = (g_h0p[0][i] + g_h0p[1][i]) + (g_h0p[2][i] + g_h0p[3][i]) + bridge_b[0];
}

// ---------------------------------------------------------------------------
// K2: gi = x0 @ w_ih^T + b_ih ; gh = h0 @ w_hh^T + b_hh   (both [B, 3H])
// ---------------------------------------------------------------------------
__global__ void k2_gates_mm(const float* __restrict__ w_ih,
                            const float* __restrict__ w_hh,
                            const float* __restrict__ b_ih,
                            const float* __restrict__ b_hh) {
    int warp = threadIdx.x >> 5;
    int lane = threadIdx.x & 31;
    int j0 = (blockIdx.x * 8 + warp) * 2;

    float ai0[B], ai1[B], ah0[B], ah1[B];
    #pragma unroll
    for (int b = 0; b < B; b++) { ai0[b] = ai1[b] = ah0[b] = ah1[b] = 0.f; }

    for (int i = 0; i < 8; i++) {
        int k = i * 128 + lane * 4;
        float4 wi0 = *(const float4*)(w_ih + (size_t)(j0 + 0) * H + k);
        float4 wi1 = *(const float4*)(w_ih + (size_t)(j0 + 1) * H + k);
        float4 wh0 = *(const float4*)(w_hh + (size_t)(j0 + 0) * H + k);
        float4 wh1 = *(const float4*)(w_hh + (size_t)(j0 + 1) * H + k);
        #pragma unroll
        for (int b = 0; b < B; b++) {
            float4 x = *(const float4*)(g_x0 + b * H + k);
            float4 h = *(const float4*)(g_h0 + b * H + k);
            ai0[b] += wi0.x * x.x + wi0.y * x.y + wi0.z * x.z + wi0.w * x.w;
            ai1[b] += wi1.x * x.x + wi1.y * x.y + wi1.z * x.z + wi1.w * x.w;
            ah0[b] += wh0.x * h.x + wh0.y * h.y + wh0.z * h.z + wh0.w * h.w;
            ah1[b] += wh1.x * h.x + wh1.y * h.y + wh1.z * h.z + wh1.w * h.w;
        }
    }

    #pragma unroll
    for (int b = 0; b < B; b++) {
        #pragma unroll
        for (int o = 16; o; o >>= 1) {
            ai0[b] += __shfl_xor_sync(0xffffffffu, ai0[b], o);
            ai1[b] += __shfl_xor_sync(0xffffffffu, ai1[b], o);
            ah0[b] += __shfl_xor_sync(0xffffffffu, ah0[b], o);
            ah1[b] += __shfl_xor_sync(0xffffffffu, ah1[b], o);
        }
    }

    if (lane == 0) {
        float bi0 = b_ih[j0], bi1 = b_ih[j0 + 1];
        float bh0 = b_hh[j0], bh1 = b_hh[j0 + 1];
        #pragma unroll
        for (int b = 0; b < B; b++) {
            g_gi[b * 3 * H + j0]     = ai0[b] + bi0;
            g_gi[b * 3 * H + j0 + 1] = ai1[b] + bi1;
            g_gh[b * 3 * H + j0]     = ah0[b] + bh0;
            g_gh[b * 3 * H + j0 + 1] = ah1[b] + bh1;
        }
    }
}

// ---------------------------------------------------------------------------
// K3: GRU cell gate math -> h1 [B,H]
// ---------------------------------------------------------------------------
__global__ void k3_gru() {
    int i = blockIdx.x * blockDim.x + threadIdx.x;
    int b = i >> 10;
    int h = i & (H - 1);
    int base = b * 3 * H + h;
    float ir = g_gi[base], iz = g_gi[base + H], in_ = g_gi[base + 2 * H];
    float hr = g_gh[base], hz = g_gh[base + H], hn  = g_gh[base + 2 * H];
    float r = 1.f / (1.f + expf(-(ir + hr)));
    float z = 1.f / (1.f + expf(-(iz + hz)));
    float n = tanhf(in_ + r * hn);
    g_h1[i] = (1.f - z) * n + z * g_h0[i];
}

// ---------------------------------------------------------------------------
// K4: logits[b,v] = h1[b,:] . proj_w[v,:] + proj_b[v]
// f32x2 packed over the BATCH dimension: smem holds h1 pre-paired
// (hs[bp][k] = (h1[2bp][k], h1[2bp+1][k])), accumulators are [4 rows][8 pairs]
// u64 = 64 regs (half of the k-packed variant) -> 2 CTAs/SM, 16 warps.
// 4 vocab rows/warp amortize smem reads; proj_w streamed with __ldcs.
// ---------------------------------------------------------------------------
__global__ __launch_bounds__(256, 2)
void k4_proj(const float* __restrict__ proj_w,
             const float* __restrict__ proj_b) {
    extern __shared__ u64 hs[];                 // BP*H u64 = 64KB
    for (int i = threadIdx.x; i < BP * H; i += 256) {
        int bp = i >> 10;
        int k  = i & (H - 1);
        unsigned lo = __float_as_uint(g_h1[(2 * bp) * H + k]);
        unsigned hi = __float_as_uint(g_h1[(2 * bp + 1) * H + k]);
        hs[i] = ((u64)hi << 32) | (u64)lo;
    }
    __syncthreads();

    int warp = threadIdx.x >> 5;
    int lane = threadIdx.x & 31;
    int v0 = (blockIdx.x * 8 + warp) * 4;
    if (v0 >= V) return;

    int r1 = min(v0 + 1, V - 1);
    int r2 = min(v0 + 2, V - 1);
    int r3 = min(v0 + 3, V - 1);
    const float4* w0 = (const float4*)(proj_w + (size_t)v0 * H);
    const float4* w1 = (const float4*)(proj_w + (size_t)r1 * H);
    const float4* w2 = (const float4*)(proj_w + (size_t)r2 * H);
    const float4* w3 = (const float4*)(proj_w + (size_t)r3 * H);

    u64 a0[BP], a1[BP], a2[BP], a3[BP];
    #pragma unroll
    for (int bp = 0; bp < BP; bp++) { a0[bp] = a1[bp] = a2[bp] = a3[bp] = 0ull; }

    #pragma unroll
    for (int i = 0; i < 8; i++) {
        int kq = i * 32 + lane;                  // float4 index into the row
        float4 p0 = __ldcs(w0 + kq);
        float4 p1 = __ldcs(w1 + kq);
        float4 p2 = __ldcs(w2 + kq);
        float4 p3 = __ldcs(w3 + kq);
        u64 q0x = dup2(p0.x), q0y = dup2(p0.y), q0z = dup2(p0.z), q0w = dup2(p0.w);
        u64 q1x = dup2(p1.x), q1y = dup2(p1.y), q1z = dup2(p1.z), q1w = dup2(p1.w);
        u64 q2x = dup2(p2.x), q2y = dup2(p2.y), q2z = dup2(p2.z), q2w = dup2(p2.w);
        u64 q3x = dup2(p3.x), q3y = dup2(p3.y), q3z = dup2(p3.z), q3w = dup2(p3.w);
        #pragma unroll
        for (int bp = 0; bp < BP; bp++) {
            const u64* xp = hs + bp * H + kq * 4;        // 4 u64 = 32B
            ulonglong2 xa = *(const ulonglong2*)(xp);     // LDS.128
            ulonglong2 xb = *(const ulonglong2*)(xp + 2); // LDS.128
            ffma2(a0[bp], q0x, xa.x); ffma2(a0[bp], q0y, xa.y);
            ffma2(a0[bp], q0z, xb.x); ffma2(a0[bp], q0w, xb.y);
            ffma2(a1[bp], q1x, xa.x); ffma2(a1[bp], q1y, xa.y);
            ffma2(a1[bp], q1z, xb.x); ffma2(a1[bp], q1w, xb.y);
            ffma2(a2[bp], q2x, xa.x); ffma2(a2[bp], q2y, xa.y);
            ffma2(a2[bp], q2z, xb.x); ffma2(a2[bp], q2w, xb.y);
            ffma2(a3[bp], q3x, xa.x); ffma2(a3[bp], q3y, xa.y);
            ffma2(a3[bp], q3z, xb.x); ffma2(a3[bp], q3w, xb.y);
        }
    }

    float pb0 = proj_b[v0];
    float pb1 = proj_b[r1];
    float pb2 = proj_b[r2];
    float pb3 = proj_b[r3];

    #pragma unroll
    for (int bp = 0; bp < BP; bp++) {
        float s0a = lo2(a0[bp]), s0b = hi2(a0[bp]);
        float s1a = lo2(a1[bp]), s1b = hi2(a1[bp]);
        float s2a = lo2(a2[bp]), s2b = hi2(a2[bp]);
        float s3a = lo2(a3[bp]), s3b = hi2(a3[bp]);
        #pragma unroll
        for (int o = 16; o; o >>= 1) {
            s0a += __shfl_xor_sync(0xffffffffu, s0a, o);
            s0b += __shfl_xor_sync(0xffffffffu, s0b, o);
            s1a += __shfl_xor_sync(0xffffffffu, s1a, o);
            s1b += __shfl_xor_sync(0xffffffffu, s1b, o);
            s2a += __shfl_xor_sync(0xffffffffu, s2a, o);
            s2b += __shfl_xor_sync(0xffffffffu, s2b, o);
            s3a += __shfl_xor_sync(0xffffffffu, s3a, o);
            s3b += __shfl_xor_sync(0xffffffffu, s3b, o);
        }
        if (lane == 0) {
            float* lga = g_logits + (size_t)(2 * bp) * V;
            float* lgb = g_logits + (size_t)(2 * bp + 1) * V;
            lga[v0] = s0a + pb0;  lgb[v0] = s0b + pb0;
            if (v0 + 1 < V) { lga[v0 + 1] = s1a + pb1;  lgb[v0 + 1] = s1b + pb1; }
            if (v0 + 2 < V) { lga[v0 + 2] = s2a + pb2;  lgb[v0 + 2] = s2b + pb2; }
            if (v0 + 3 < V) { lga[v0 + 3] = s3a + pb3;  lgb[v0 + 3] = s3b + pb3; }
        }
    }
}

// ---------------------------------------------------------------------------
// K5: per-batch max and log-sum-exp over V (logits hot in L2)
// ---------------------------------------------------------------------------
__global__ void k5_lse() {
    int b = blockIdx.x;
    __shared__ float red[256];
    const float* lg = g_logits + (size_t)b * V;

    float m = -1e30f;
    for (int v = threadIdx.x; v < V; v += 256) m = fmaxf(m, lg[v]);
    red[threadIdx.x] = m;
    __syncthreads();
    for (int s = 128; s; s >>= 1) {
        if (threadIdx.x < s) red[threadIdx.x] = fmaxf(red[threadIdx.x], red[threadIdx.x + s]);
        __syncthreads();
    }
    m = red[0];
    __syncthreads();

    float sum = 0.f;
    for (int v = threadIdx.x; v < V; v += 256) sum += expf(lg[v] - m);
    red[threadIdx.x] = sum;
    __syncthreads();
    for (int s = 128; s; s >>= 1) {
        if (threadIdx.x < s) red[threadIdx.x] += red[threadIdx.x + s];
        __syncthreads();
    }
    if (threadIdx.x == 0) { g_m[b] = m; g_l[b] = logf(red[0]); }
}

// ---------------------------------------------------------------------------
// K6: out[b,t,v] = logits[b,v] - m[b] - lse[b]  broadcast over t (127)
// ---------------------------------------------------------------------------
__global__ void k6_out(float* __restrict__ out) {
    int v = blockIdx.x * blockDim.x + threadIdx.x;
    int b = blockIdx.y;
    if (v >= V) return;
    float val = g_logits[(size_t)b * V + v] - g_m[b] - g_l[b];
    float* o = out + (size_t)b * T * V + v;
    #pragma unroll 8
    for (int t = 0; t < T; t++) o[(size_t)t * V] = val;
}

// ---------------------------------------------------------------------------
extern "C" void kernel_launch(void* const* d_in, const int* in_sizes, int n_in,
                              void* d_out, int out_size) {
    const int*   input    = (const int*)d_in[0];
    const float* hidden   = (const float*)d_in[1];
    const float* emb      = (const float*)d_in[2];
    const float* bridge_w = (const float*)d_in[3];
    const float* bridge_b = (const float*)d_in[4];
    const float* w_ih     = (const float*)d_in[5];
    const float* w_hh     = (const float*)d_in[6];
    const float* b_ih     = (const float*)d_in[7];
    const float* b_hh     = (const float*)d_in[8];
    const float* proj_w   = (const float*)d_in[9];
    const float* proj_b   = (const float*)d_in[10];
    float* out = (float*)d_out;

    cudaFuncSetAttribute(k4_proj, cudaFuncAttributeMaxDynamicSharedMemorySize,
                         BP * H * (int)sizeof(u64));

    dim3 g1(64, 4);
    k1a_bridge_part<<<g1, 256>>>(hidden, bridge_w);
    k1b_combine<<<64, 256>>>(input, emb, bridge_b);
    k2_gates_mm<<<192, 256>>>(w_ih, w_hh, b_ih, b_hh);
    k3_gru<<<(B * H) / 256, 256>>>();
    int blocks4 = (V + 31) / 32;   // 8 warps x 4 rows per block
    k4_proj<<<blocks4, 256, BP * H * sizeof(u64)>>>(proj_w, proj_b);
    k5_lse<<<B, 256>>>();
    dim3 g6((V + 255) / 256, B);
    k6_out<<<g6, 256>>>(out);
}

// round 6
// speedup vs baseline: 1.3911x; 1.3911x over previous
#include <cuda_runtime.h>
#include <math.h>

#define B 16
#define L 128
#define H 1024
#define V 50257
#define T (L-1)

// ---- scratch (no allocations allowed) ----
__device__ float g_x0[B * H];
__device__ float g_h0[B * H];
__device__ float g_gi[B * 3 * H];
__device__ float g_gh[B * 3 * H];
__device__ float g_h1[B * H];
__device__ float g_logits[(size_t)B * V];
__device__ float g_m[B];
__device__ float g_l[B];

// ---------------------------------------------------------------------------
// K1: x0 = relu(emb[input[:,0]]);  h0[b,h] = sum_l hidden[b,l,h]*bw[l] + bb
// one thread per (b,h); coalesced over h. (single launch so k4 is launch #4)
// ---------------------------------------------------------------------------
__global__ void k1_embed_bridge(const int* __restrict__ input,
                                const float* __restrict__ hidden,
                                const float* __restrict__ emb,
                                const float* __restrict__ bridge_w,
                                const float* __restrict__ bridge_b) {
    __shared__ float bw[L];
    int tid = threadIdx.x;
    if (tid < L) bw[tid] = bridge_w[tid];
    __syncthreads();

    int i = blockIdx.x * blockDim.x + tid;   // 0 .. B*H-1
    int b = i >> 10;
    int h = i & (H - 1);

    int tok = input[b * L];                  // input[:,0]
    g_x0[i] = fmaxf(emb[(size_t)tok * H + h], 0.0f);

    const float* hp = hidden + (size_t)b * L * H + h;
    float a0 = 0.f, a1 = 0.f, a2 = 0.f, a3 = 0.f;
    #pragma unroll
    for (int l = 0; l < L; l += 4) {
        a0 += hp[(l + 0) * H] * bw[l + 0];
        a1 += hp[(l + 1) * H] * bw[l + 1];
        a2 += hp[(l + 2) * H] * bw[l + 2];
        a3 += hp[(l + 3) * H] * bw[l + 3];
    }
    g_h0[i] = (a0 + a1) + (a2 + a3) + bridge_b[0];
}

// ---------------------------------------------------------------------------
// K2: gi = x0 @ w_ih^T + b_ih ; gh = h0 @ w_hh^T + b_hh   (both [B, 3H])
// ---------------------------------------------------------------------------
__global__ void k2_gates_mm(const float* __restrict__ w_ih,
                            const float* __restrict__ w_hh,
                            const float* __restrict__ b_ih,
                            const float* __restrict__ b_hh) {
    int warp = threadIdx.x >> 5;
    int lane = threadIdx.x & 31;
    int j0 = (blockIdx.x * 8 + warp) * 2;

    float ai0[B], ai1[B], ah0[B], ah1[B];
    #pragma unroll
    for (int b = 0; b < B; b++) { ai0[b] = ai1[b] = ah0[b] = ah1[b] = 0.f; }

    for (int i = 0; i < 8; i++) {
        int k = i * 128 + lane * 4;
        float4 wi0 = *(const float4*)(w_ih + (size_t)(j0 + 0) * H + k);
        float4 wi1 = *(const float4*)(w_ih + (size_t)(j0 + 1) * H + k);
        float4 wh0 = *(const float4*)(w_hh + (size_t)(j0 + 0) * H + k);
        float4 wh1 = *(const float4*)(w_hh + (size_t)(j0 + 1) * H + k);
        #pragma unroll
        for (int b = 0; b < B; b++) {
            float4 x = *(const float4*)(g_x0 + b * H + k);
            float4 h = *(const float4*)(g_h0 + b * H + k);
            ai0[b] += wi0.x * x.x + wi0.y * x.y + wi0.z * x.z + wi0.w * x.w;
            ai1[b] += wi1.x * x.x + wi1.y * x.y + wi1.z * x.z + wi1.w * x.w;
            ah0[b] += wh0.x * h.x + wh0.y * h.y + wh0.z * h.z + wh0.w * h.w;
            ah1[b] += wh1.x * h.x + wh1.y * h.y + wh1.z * h.z + wh1.w * h.w;
        }
    }

    #pragma unroll
    for (int b = 0; b < B; b++) {
        #pragma unroll
        for (int o = 16; o; o >>= 1) {
            ai0[b] += __shfl_xor_sync(0xffffffffu, ai0[b], o);
            ai1[b] += __shfl_xor_sync(0xffffffffu, ai1[b], o);
            ah0[b] += __shfl_xor_sync(0xffffffffu, ah0[b], o);
            ah1[b] += __shfl_xor_sync(0xffffffffu, ah1[b], o);
        }
    }

    if (lane == 0) {
        float bi0 = b_ih[j0], bi1 = b_ih[j0 + 1];
        float bh0 = b_hh[j0], bh1 = b_hh[j0 + 1];
        #pragma unroll
        for (int b = 0; b < B; b++) {
            g_gi[b * 3 * H + j0]     = ai0[b] + bi0;
            g_gi[b * 3 * H + j0 + 1] = ai1[b] + bi1;
            g_gh[b * 3 * H + j0]     = ah0[b] + bh0;
            g_gh[b * 3 * H + j0 + 1] = ah1[b] + bh1;
        }
    }
}

// ---------------------------------------------------------------------------
// K3: GRU cell gate math -> h1 [B,H]
// ---------------------------------------------------------------------------
__global__ void k3_gru() {
    int i = blockIdx.x * blockDim.x + threadIdx.x;
    int b = i >> 10;
    int h = i & (H - 1);
    int base = b * 3 * H + h;
    float ir = g_gi[base], iz = g_gi[base + H], in_ = g_gi[base + 2 * H];
    float hr = g_gh[base], hz = g_gh[base + H], hn  = g_gh[base + 2 * H];
    float r = 1.f / (1.f + expf(-(ir + hr)));
    float z = 1.f / (1.f + expf(-(iz + hz)));
    float n = tanhf(in_ + r * hn);
    g_h1[i] = (1.f - z) * n + z * g_h0[i];
}

// ---------------------------------------------------------------------------
// K4: logits[b,v] = h1[b,:] . proj_w[v,:] + proj_b[v]
// Round-2 proven structure (4 vocab rows/warp, h1 in smem, scalar FFMA)
// + 1-deep software prefetch of the streamed proj_w loads.
// ---------------------------------------------------------------------------
__global__ __launch_bounds__(256, 2)
void k4_proj(const float* __restrict__ proj_w,
             const float* __restrict__ proj_b) {
    extern __shared__ float hs[];                 // B*H floats = 64KB
    for (int i = threadIdx.x; i < B * H; i += 256) hs[i] = g_h1[i];
    __syncthreads();

    int warp = threadIdx.x >> 5;
    int lane = threadIdx.x & 31;
    int v0 = (blockIdx.x * 8 + warp) * 4;
    if (v0 >= V) return;

    int r1 = min(v0 + 1, V - 1);
    int r2 = min(v0 + 2, V - 1);
    int r3 = min(v0 + 3, V - 1);
    const float4* w0 = (const float4*)(proj_w + (size_t)v0 * H);
    const float4* w1 = (const float4*)(proj_w + (size_t)r1 * H);
    const float4* w2 = (const float4*)(proj_w + (size_t)r2 * H);
    const float4* w3 = (const float4*)(proj_w + (size_t)r3 * H);

    float a0[B], a1[B], a2[B], a3[B];
    #pragma unroll
    for (int b = 0; b < B; b++) { a0[b] = a1[b] = a2[b] = a3[b] = 0.f; }

    // prefetch iter 0
    float4 p0 = __ldcs(w0 + lane);
    float4 p1 = __ldcs(w1 + lane);
    float4 p2 = __ldcs(w2 + lane);
    float4 p3 = __ldcs(w3 + lane);

    #pragma unroll
    for (int i = 0; i < 8; i++) {
        int kq = i * 32 + lane;                    // float4 index into row
        float4 c0 = p0, c1 = p1, c2 = p2, c3 = p3;
        if (i < 7) {                               // prefetch iter i+1
            int kn = kq + 32;
            p0 = __ldcs(w0 + kn);
            p1 = __ldcs(w1 + kn);
            p2 = __ldcs(w2 + kn);
            p3 = __ldcs(w3 + kn);
        }
        #pragma unroll
        for (int b = 0; b < B; b++) {
            float4 x = ((const float4*)(hs + b * H))[kq];
            a0[b] += c0.x * x.x + c0.y * x.y + c0.z * x.z + c0.w * x.w;
            a1[b] += c1.x * x.x + c1.y * x.y + c1.z * x.z + c1.w * x.w;
            a2[b] += c2.x * x.x + c2.y * x.y + c2.z * x.z + c2.w * x.w;
            a3[b] += c3.x * x.x + c3.y * x.y + c3.z * x.z + c3.w * x.w;
        }
    }

    #pragma unroll
    for (int b = 0; b < B; b++) {
        #pragma unroll
        for (int o = 16; o; o >>= 1) {
            a0[b] += __shfl_xor_sync(0xffffffffu, a0[b], o);
            a1[b] += __shfl_xor_sync(0xffffffffu, a1[b], o);
            a2[b] += __shfl_xor_sync(0xffffffffu, a2[b], o);
            a3[b] += __shfl_xor_sync(0xffffffffu, a3[b], o);
        }
    }

    if (lane == 0) {
        float pb0 = proj_b[v0];
        float pb1 = proj_b[r1];
        float pb2 = proj_b[r2];
        float pb3 = proj_b[r3];
        #pragma unroll
        for (int b = 0; b < B; b++) {
            float* lg = g_logits + (size_t)b * V;
            lg[v0] = a0[b] + pb0;
            if (v0 + 1 < V) lg[v0 + 1] = a1[b] + pb1;
            if (v0 + 2 < V) lg[v0 + 2] = a2[b] + pb2;
            if (v0 + 3 < V) lg[v0 + 3] = a3[b] + pb3;
        }
    }
}

// ---------------------------------------------------------------------------
// K5: per-batch max and log-sum-exp over V (logits hot in L2)
// ---------------------------------------------------------------------------
__global__ void k5_lse() {
    int b = blockIdx.x;
    __shared__ float red[256];
    const float* lg = g_logits + (size_t)b * V;

    float m = -1e30f;
    for (int v = threadIdx.x; v < V; v += 256) m = fmaxf(m, lg[v]);
    red[threadIdx.x] = m;
    __syncthreads();
    for (int s = 128; s; s >>= 1) {
        if (threadIdx.x < s) red[threadIdx.x] = fmaxf(red[threadIdx.x], red[threadIdx.x + s]);
        __syncthreads();
    }
    m = red[0];
    __syncthreads();

    float sum = 0.f;
    for (int v = threadIdx.x; v < V; v += 256) sum += expf(lg[v] - m);
    red[threadIdx.x] = sum;
    __syncthreads();
    for (int s = 128; s; s >>= 1) {
        if (threadIdx.x < s) red[threadIdx.x] += red[threadIdx.x + s];
        __syncthreads();
    }
    if (threadIdx.x == 0) { g_m[b] = m; g_l[b] = logf(red[0]); }
}

// ---------------------------------------------------------------------------
// K6: out[b,t,v] = logits[b,v] - m[b] - lse[b]  broadcast over t (127)
// ---------------------------------------------------------------------------
__global__ void k6_out(float* __restrict__ out) {
    int v = blockIdx.x * blockDim.x + threadIdx.x;
    int b = blockIdx.y;
    if (v >= V) return;
    float val = g_logits[(size_t)b * V + v] - g_m[b] - g_l[b];
    float* o = out + (size_t)b * T * V + v;
    #pragma unroll 8
    for (int t = 0; t < T; t++) o[(size_t)t * V] = val;
}

// ---------------------------------------------------------------------------
extern "C" void kernel_launch(void* const* d_in, const int* in_sizes, int n_in,
                              void* d_out, int out_size) {
    const int*   input    = (const int*)d_in[0];
    const float* hidden   = (const float*)d_in[1];
    const float* emb      = (const float*)d_in[2];
    const float* bridge_w = (const float*)d_in[3];
    const float* bridge_b = (const float*)d_in[4];
    const float* w_ih     = (const float*)d_in[5];
    const float* w_hh     = (const float*)d_in[6];
    const float* b_ih     = (const float*)d_in[7];
    const float* b_hh     = (const float*)d_in[8];
    const float* proj_w   = (const float*)d_in[9];
    const float* proj_b   = (const float*)d_in[10];
    float* out = (float*)d_out;

    cudaFuncSetAttribute(k4_proj, cudaFuncAttributeMaxDynamicSharedMemorySize,
                         B * H * (int)sizeof(float));

    // k4 is launch #4 -> lands in the ncu-profiled slot
    k1_embed_bridge<<<(B * H) / 256, 256>>>(input, hidden, emb, bridge_w, bridge_b);
    k2_gates_mm<<<192, 256>>>(w_ih, w_hh, b_ih, b_hh);
    k3_gru<<<(B * H) / 256, 256>>>();
    int blocks4 = (V + 31) / 32;   // 8 warps x 4 rows per block
    k4_proj<<<blocks4, 256, B * H * sizeof(float)>>>(proj_w, proj_b);
    k5_lse<<<B, 256>>>();
    dim3 g6((V + 255) / 256, B);
    k6_out<<<g6, 256>>>(out);
}

// round 7
// speedup vs baseline: 1.4537x; 1.0450x over previous
#include <cuda_runtime.h>
#include <math.h>

#define B 16
#define L 128
#define H 1024
#define V 50257
#define T (L-1)
#define BP (B/2)

typedef unsigned long long u64;

// ---- scratch (no allocations allowed) ----
__device__ float g_x0[B * H];
__device__ float g_h0[B * H];
__device__ float g_gi[B * 3 * H];
__device__ float g_gh[B * 3 * H];
__device__ float g_h1[B * H];
__device__ float g_logits[(size_t)B * V];
__device__ float g_m[B];
__device__ float g_l[B];

// packed f32x2 FMA: d = a*b + d (2 MACs / SASS FFMA2)
__device__ __forceinline__ void ffma2(u64 &d, u64 a, u64 b) {
    asm("fma.rn.f32x2 %0, %1, %2, %0;" : "+l"(d) : "l"(a), "l"(b));
}
__device__ __forceinline__ u64 dup2(float f) {
    u64 r;
    asm("mov.b64 %0, {%1, %1};" : "=l"(r) : "f"(f));
    return r;
}
__device__ __forceinline__ float lo2(u64 a) { return __uint_as_float((unsigned)a); }
__device__ __forceinline__ float hi2(u64 a) { return __uint_as_float((unsigned)(a >> 32)); }

// XOR swizzle on u64 index: flips the 16B-granule bit on alternating 128B lines
__device__ __forceinline__ int swz(int i) { return i ^ (((i >> 4) & 1) << 1); }

// ---------------------------------------------------------------------------
// K1: x0 = relu(emb[input[:,0]]);  h0[b,h] = sum_l hidden[b,l,h]*bw[l] + bb
// ---------------------------------------------------------------------------
__global__ void k1_embed_bridge(const int* __restrict__ input,
                                const float* __restrict__ hidden,
                                const float* __restrict__ emb,
                                const float* __restrict__ bridge_w,
                                const float* __restrict__ bridge_b) {
    __shared__ float bw[L];
    int tid = threadIdx.x;
    if (tid < L) bw[tid] = bridge_w[tid];
    __syncthreads();

    int i = blockIdx.x * blockDim.x + tid;
    int b = i >> 10;
    int h = i & (H - 1);

    int tok = input[b * L];
    g_x0[i] = fmaxf(emb[(size_t)tok * H + h], 0.0f);

    const float* hp = hidden + (size_t)b * L * H + h;
    float a0 = 0.f, a1 = 0.f, a2 = 0.f, a3 = 0.f;
    #pragma unroll
    for (int l = 0; l < L; l += 4) {
        a0 += hp[(l + 0) * H] * bw[l + 0];
        a1 += hp[(l + 1) * H] * bw[l + 1];
        a2 += hp[(l + 2) * H] * bw[l + 2];
        a3 += hp[(l + 3) * H] * bw[l + 3];
    }
    g_h0[i] = (a0 + a1) + (a2 + a3) + bridge_b[0];
}

// ---------------------------------------------------------------------------
// K2: gi = x0 @ w_ih^T + b_ih ; gh = h0 @ w_hh^T + b_hh   (both [B, 3H])
// ---------------------------------------------------------------------------
__global__ void k2_gates_mm(const float* __restrict__ w_ih,
                            const float* __restrict__ w_hh,
                            const float* __restrict__ b_ih,
                            const float* __restrict__ b_hh) {
    int warp = threadIdx.x >> 5;
    int lane = threadIdx.x & 31;
    int j0 = (blockIdx.x * 8 + warp) * 2;

    float ai0[B], ai1[B], ah0[B], ah1[B];
    #pragma unroll
    for (int b = 0; b < B; b++) { ai0[b] = ai1[b] = ah0[b] = ah1[b] = 0.f; }

    for (int i = 0; i < 8; i++) {
        int k = i * 128 + lane * 4;
        float4 wi0 = *(const float4*)(w_ih + (size_t)(j0 + 0) * H + k);
        float4 wi1 = *(const float4*)(w_ih + (size_t)(j0 + 1) * H + k);
        float4 wh0 = *(const float4*)(w_hh + (size_t)(j0 + 0) * H + k);
        float4 wh1 = *(const float4*)(w_hh + (size_t)(j0 + 1) * H + k);
        #pragma unroll
        for (int b = 0; b < B; b++) {
            float4 x = *(const float4*)(g_x0 + b * H + k);
            float4 h = *(const float4*)(g_h0 + b * H + k);
            ai0[b] += wi0.x * x.x + wi0.y * x.y + wi0.z * x.z + wi0.w * x.w;
            ai1[b] += wi1.x * x.x + wi1.y * x.y + wi1.z * x.z + wi1.w * x.w;
            ah0[b] += wh0.x * h.x + wh0.y * h.y + wh0.z * h.z + wh0.w * h.w;
            ah1[b] += wh1.x * h.x + wh1.y * h.y + wh1.z * h.z + wh1.w * h.w;
        }
    }

    #pragma unroll
    for (int b = 0; b < B; b++) {
        #pragma unroll
        for (int o = 16; o; o >>= 1) {
            ai0[b] += __shfl_xor_sync(0xffffffffu, ai0[b], o);
            ai1[b] += __shfl_xor_sync(0xffffffffu, ai1[b], o);
            ah0[b] += __shfl_xor_sync(0xffffffffu, ah0[b], o);
            ah1[b] += __shfl_xor_sync(0xffffffffu, ah1[b], o);
        }
    }

    if (lane == 0) {
        float bi0 = b_ih[j0], bi1 = b_ih[j0 + 1];
        float bh0 = b_hh[j0], bh1 = b_hh[j0 + 1];
        #pragma unroll
        for (int b = 0; b < B; b++) {
            g_gi[b * 3 * H + j0]     = ai0[b] + bi0;
            g_gi[b * 3 * H + j0 + 1] = ai1[b] + bi1;
            g_gh[b * 3 * H + j0]     = ah0[b] + bh0;
            g_gh[b * 3 * H + j0 + 1] = ah1[b] + bh1;
        }
    }
}

// ---------------------------------------------------------------------------
// K3: GRU cell gate math -> h1 [B,H]
// ---------------------------------------------------------------------------
__global__ void k3_gru() {
    int i = blockIdx.x * blockDim.x + threadIdx.x;
    int b = i >> 10;
    int h = i & (H - 1);
    int base = b * 3 * H + h;
    float ir = g_gi[base], iz = g_gi[base + H], in_ = g_gi[base + 2 * H];
    float hr = g_gh[base], hz = g_gh[base + H], hn  = g_gh[base + 2 * H];
    float r = 1.f / (1.f + expf(-(ir + hr)));
    float z = 1.f / (1.f + expf(-(iz + hz)));
    float n = tanhf(in_ + r * hn);
    g_h1[i] = (1.f - z) * n + z * g_h0[i];
}

// ---------------------------------------------------------------------------
// K4: logits[b,v] = h1[b,:] . proj_w[v,:] + proj_b[v]
// Batch-packed f32x2 (acc lo/hi = batches 2bp/2bp+1): 128 FFMA2/iter instead
// of 256 FFMA. h1 pairs live in smem with an XOR swizzle so the 32B-lane-
// stride LDS.128 pattern is bank-conflict-free (round 5's failure mode).
// 64 accumulator regs -> 2 CTAs/SM. proj_w streamed with __ldcs.
// ---------------------------------------------------------------------------
__global__ __launch_bounds__(256, 2)
void k4_proj(const float* __restrict__ proj_w,
             const float* __restrict__ proj_b) {
    extern __shared__ u64 hs[];                 // BP*H u64 = 64KB, swizzled
    for (int i = threadIdx.x; i < BP * H; i += 256) {
        int bp = i >> 10;
        int k  = i & (H - 1);
        unsigned lo = __float_as_uint(g_h1[(2 * bp) * H + k]);
        unsigned hi = __float_as_uint(g_h1[(2 * bp + 1) * H + k]);
        hs[swz(i)] = ((u64)hi << 32) | (u64)lo;
    }
    __syncthreads();

    int warp = threadIdx.x >> 5;
    int lane = threadIdx.x & 31;
    int v0 = (blockIdx.x * 8 + warp) * 4;
    if (v0 >= V) return;

    int r1 = min(v0 + 1, V - 1);
    int r2 = min(v0 + 2, V - 1);
    int r3 = min(v0 + 3, V - 1);
    const float4* w0 = (const float4*)(proj_w + (size_t)v0 * H);
    const float4* w1 = (const float4*)(proj_w + (size_t)r1 * H);
    const float4* w2 = (const float4*)(proj_w + (size_t)r2 * H);
    const float4* w3 = (const float4*)(proj_w + (size_t)r3 * H);

    u64 a0[BP], a1[BP], a2[BP], a3[BP];
    #pragma unroll
    for (int bp = 0; bp < BP; bp++) { a0[bp] = a1[bp] = a2[bp] = a3[bp] = 0ull; }

    #pragma unroll
    for (int i = 0; i < 8; i++) {
        int kq = i * 32 + lane;                  // float4 index into the row
        float4 p0 = __ldcs(w0 + kq);
        float4 p1 = __ldcs(w1 + kq);
        float4 p2 = __ldcs(w2 + kq);
        float4 p3 = __ldcs(w3 + kq);
        u64 q0x = dup2(p0.x), q0y = dup2(p0.y), q0z = dup2(p0.z), q0w = dup2(p0.w);
        u64 q1x = dup2(p1.x), q1y = dup2(p1.y), q1z = dup2(p1.z), q1w = dup2(p1.w);
        u64 q2x = dup2(p2.x), q2y = dup2(p2.y), q2z = dup2(p2.z), q2w = dup2(p2.w);
        u64 q3x = dup2(p3.x), q3y = dup2(p3.y), q3z = dup2(p3.z), q3w = dup2(p3.w);
        #pragma unroll
        for (int bp = 0; bp < BP; bp++) {
            int idx = bp * 1024 + kq * 4;              // u64 index of k0
            int f   = ((idx >> 4) & 1) << 1;           // same for idx..idx+3
            ulonglong2 xa = *(const ulonglong2*)(hs + (idx ^ f));        // k0,k1
            ulonglong2 xb = *(const ulonglong2*)(hs + ((idx + 2) ^ f));  // k2,k3
            ffma2(a0[bp], q0x, xa.x); ffma2(a0[bp], q0y, xa.y);
            ffma2(a0[bp], q0z, xb.x); ffma2(a0[bp], q0w, xb.y);
            ffma2(a1[bp], q1x, xa.x); ffma2(a1[bp], q1y, xa.y);
            ffma2(a1[bp], q1z, xb.x); ffma2(a1[bp], q1w, xb.y);
            ffma2(a2[bp], q2x, xa.x); ffma2(a2[bp], q2y, xa.y);
            ffma2(a2[bp], q2z, xb.x); ffma2(a2[bp], q2w, xb.y);
            ffma2(a3[bp], q3x, xa.x); ffma2(a3[bp], q3y, xa.y);
            ffma2(a3[bp], q3z, xb.x); ffma2(a3[bp], q3w, xb.y);
        }
    }

    float pb0 = proj_b[v0];
    float pb1 = proj_b[r1];
    float pb2 = proj_b[r2];
    float pb3 = proj_b[r3];

    #pragma unroll
    for (int bp = 0; bp < BP; bp++) {
        float s0a = lo2(a0[bp]), s0b = hi2(a0[bp]);
        float s1a = lo2(a1[bp]), s1b = hi2(a1[bp]);
        float s2a = lo2(a2[bp]), s2b = hi2(a2[bp]);
        float s3a = lo2(a3[bp]), s3b = hi2(a3[bp]);
        #pragma unroll
        for (int o = 16; o; o >>= 1) {
            s0a += __shfl_xor_sync(0xffffffffu, s0a, o);
            s0b += __shfl_xor_sync(0xffffffffu, s0b, o);
            s1a += __shfl_xor_sync(0xffffffffu, s1a, o);
            s1b += __shfl_xor_sync(0xffffffffu, s1b, o);
            s2a += __shfl_xor_sync(0xffffffffu, s2a, o);
            s2b += __shfl_xor_sync(0xffffffffu, s2b, o);
            s3a += __shfl_xor_sync(0xffffffffu, s3a, o);
            s3b += __shfl_xor_sync(0xffffffffu, s3b, o);
        }
        if (lane == 0) {
            float* lga = g_logits + (size_t)(2 * bp) * V;
            float* lgb = g_logits + (size_t)(2 * bp + 1) * V;
            lga[v0] = s0a + pb0;  lgb[v0] = s0b + pb0;
            if (v0 + 1 < V) { lga[v0 + 1] = s1a + pb1;  lgb[v0 + 1] = s1b + pb1; }
            if (v0 + 2 < V) { lga[v0 + 2] = s2a + pb2;  lgb[v0 + 2] = s2b + pb2; }
            if (v0 + 3 < V) { lga[v0 + 3] = s3a + pb3;  lgb[v0 + 3] = s3b + pb3; }
        }
    }
}

// ---------------------------------------------------------------------------
// K5: per-batch max and log-sum-exp over V (logits hot in L2)
// ---------------------------------------------------------------------------
__global__ void k5_lse() {
    int b = blockIdx.x;
    __shared__ float red[256];
    const float* lg = g_logits + (size_t)b * V;

    float m = -1e30f;
    for (int v = threadIdx.x; v < V; v += 256) m = fmaxf(m, lg[v]);
    red[threadIdx.x] = m;
    __syncthreads();
    for (int s = 128; s; s >>= 1) {
        if (threadIdx.x < s) red[threadIdx.x] = fmaxf(red[threadIdx.x], red[threadIdx.x + s]);
        __syncthreads();
    }
    m = red[0];
    __syncthreads();

    float sum = 0.f;
    for (int v = threadIdx.x; v < V; v += 256) sum += expf(lg[v] - m);
    red[threadIdx.x] = sum;
    __syncthreads();
    for (int s = 128; s; s >>= 1) {
        if (threadIdx.x < s) red[threadIdx.x] += red[threadIdx.x + s];
        __syncthreads();
    }
    if (threadIdx.x == 0) { g_m[b] = m; g_l[b] = logf(red[0]); }
}

// ---------------------------------------------------------------------------
// K6: out[b,t,v] = logits[b,v] - m[b] - lse[b]  broadcast over t (127)
// ---------------------------------------------------------------------------
__global__ void k6_out(float* __restrict__ out) {
    int v = blockIdx.x * blockDim.x + threadIdx.x;
    int b = blockIdx.y;
    if (v >= V) return;
    float val = g_logits[(size_t)b * V + v] - g_m[b] - g_l[b];
    float* o = out + (size_t)b * T * V + v;
    #pragma unroll 8
    for (int t = 0; t < T; t++) o[(size_t)t * V] = val;
}

// ---------------------------------------------------------------------------
extern "C" void kernel_launch(void* const* d_in, const int* in_sizes, int n_in,
                              void* d_out, int out_size) {
    const int*   input    = (const int*)d_in[0];
    const float* hidden   = (const float*)d_in[1];
    const float* emb      = (const float*)d_in[2];
    const float* bridge_w = (const float*)d_in[3];
    const float* bridge_b = (const float*)d_in[4];
    const float* w_ih     = (const float*)d_in[5];
    const float* w_hh     = (const float*)d_in[6];
    const float* b_ih     = (const float*)d_in[7];
    const float* b_hh     = (const float*)d_in[8];
    const float* proj_w   = (const float*)d_in[9];
    const float* proj_b   = (const float*)d_in[10];
    float* out = (float*)d_out;

    cudaFuncSetAttribute(k4_proj, cudaFuncAttributeMaxDynamicSharedMemorySize,
                         BP * H * (int)sizeof(u64));

    // k4 is launch #4 -> lands in the ncu-profiled slot
    k1_embed_bridge<<<(B * H) / 256, 256>>>(input, hidden, emb, bridge_w, bridge_b);
    k2_gates_mm<<<192, 256>>>(w_ih, w_hh, b_ih, b_hh);
    k3_gru<<<(B * H) / 256, 256>>>();
    int blocks4 = (V + 31) / 32;   // 8 warps x 4 rows per block
    k4_proj<<<blocks4, 256, BP * H * sizeof(u64)>>>(proj_w, proj_b);
    k5_lse<<<B, 256>>>();
    dim3 g6((V + 255) / 256, B);
    k6_out<<<g6, 256>>>(out);
}

// round 8
// speedup vs baseline: 1.4686x; 1.0103x over previous
#include <cuda_runtime.h>
#include <math.h>

#define B 16
#define L 128
#define H 1024
#define V 50257
#define T (L-1)
#define BP (B/2)

typedef unsigned long long u64;

// ---- scratch (no allocations allowed) ----
__device__ float g_x0[B * H];
__device__ float g_h0[B * H];
__device__ float g_gi[B * 3 * H];
__device__ float g_gh[B * 3 * H];
__device__ float g_h1[B * H];
__device__ float g_logits[(size_t)B * V];
__device__ float g_m[B];
__device__ float g_l[B];

// packed f32x2 FMA: d = a*b + d (2 MACs / SASS FFMA2)
__device__ __forceinline__ void ffma2(u64 &d, u64 a, u64 b) {
    asm("fma.rn.f32x2 %0, %1, %2, %0;" : "+l"(d) : "l"(a), "l"(b));
}
__device__ __forceinline__ u64 dup2(float f) {
    u64 r;
    asm("mov.b64 %0, {%1, %1};" : "=l"(r) : "f"(f));
    return r;
}
__device__ __forceinline__ float lo2(u64 a) { return __uint_as_float((unsigned)a); }
__device__ __forceinline__ float hi2(u64 a) { return __uint_as_float((unsigned)(a >> 32)); }

// XOR swizzle on u64 index: flips the 16B-granule bit on alternating 128B lines
__device__ __forceinline__ int swz(int i) { return i ^ (((i >> 4) & 1) << 1); }

// cp.async 16B, L2-only path (streaming)
__device__ __forceinline__ void cpasync16(unsigned dst, const void* src) {
    asm volatile("cp.async.cg.shared.global [%0], [%1], 16;" :: "r"(dst), "l"(src) : "memory");
}
__device__ __forceinline__ void cpcommit() {
    asm volatile("cp.async.commit_group;" ::: "memory");
}
template <int N>
__device__ __forceinline__ void cpwait() {
    asm volatile("cp.async.wait_group %0;" :: "n"(N) : "memory");
}

// ---------------------------------------------------------------------------
// K1: x0 = relu(emb[input[:,0]]);  h0[b,h] = sum_l hidden[b,l,h]*bw[l] + bb
// 4 threads per (b,h), each reducing 32 l-values; smem combine.
// grid = 256 blocks -> chip filled (vs 64 before).
// ---------------------------------------------------------------------------
__global__ void k1_embed_bridge(const int* __restrict__ input,
                                const float* __restrict__ hidden,
                                const float* __restrict__ emb,
                                const float* __restrict__ bridge_w,
                                const float* __restrict__ bridge_b) {
    __shared__ float bw[L];
    __shared__ float part[4][64];
    int tid = threadIdx.x;
    if (tid < L) bw[tid] = bridge_w[tid];
    __syncthreads();

    int slot = tid & 63;            // which (b,h) within block
    int lc   = tid >> 6;            // l-chunk 0..3
    int i = blockIdx.x * 64 + slot; // 0 .. B*H-1
    int b = i >> 10;
    int h = i & (H - 1);

    const float* hp = hidden + (size_t)b * L * H + (size_t)(lc * 32) * H + h;
    float a0 = 0.f, a1 = 0.f, a2 = 0.f, a3 = 0.f;
    #pragma unroll
    for (int l = 0; l < 32; l += 4) {
        a0 += hp[(l + 0) * H] * bw[lc * 32 + l + 0];
        a1 += hp[(l + 1) * H] * bw[lc * 32 + l + 1];
        a2 += hp[(l + 2) * H] * bw[lc * 32 + l + 2];
        a3 += hp[(l + 3) * H] * bw[lc * 32 + l + 3];
    }
    part[lc][slot] = (a0 + a1) + (a2 + a3);
    __syncthreads();

    if (lc == 0) {
        int tok = input[b * L];
        g_x0[i] = fmaxf(emb[(size_t)tok * H + h], 0.0f);
        g_h0[i] = (part[0][slot] + part[1][slot]) +
                  (part[2][slot] + part[3][slot]) + bridge_b[0];
    }
}

// ---------------------------------------------------------------------------
// K2: gi = x0 @ w_ih^T + b_ih ; gh = h0 @ w_hh^T + b_hh   (both [B, 3H])
// ---------------------------------------------------------------------------
__global__ void k2_gates_mm(const float* __restrict__ w_ih,
                            const float* __restrict__ w_hh,
                            const float* __restrict__ b_ih,
                            const float* __restrict__ b_hh) {
    int warp = threadIdx.x >> 5;
    int lane = threadIdx.x & 31;
    int j0 = (blockIdx.x * 8 + warp) * 2;

    float ai0[B], ai1[B], ah0[B], ah1[B];
    #pragma unroll
    for (int b = 0; b < B; b++) { ai0[b] = ai1[b] = ah0[b] = ah1[b] = 0.f; }

    for (int i = 0; i < 8; i++) {
        int k = i * 128 + lane * 4;
        float4 wi0 = *(const float4*)(w_ih + (size_t)(j0 + 0) * H + k);
        float4 wi1 = *(const float4*)(w_ih + (size_t)(j0 + 1) * H + k);
        float4 wh0 = *(const float4*)(w_hh + (size_t)(j0 + 0) * H + k);
        float4 wh1 = *(const float4*)(w_hh + (size_t)(j0 + 1) * H + k);
        #pragma unroll
        for (int b = 0; b < B; b++) {
            float4 x = *(const float4*)(g_x0 + b * H + k);
            float4 h = *(const float4*)(g_h0 + b * H + k);
            ai0[b] += wi0.x * x.x + wi0.y * x.y + wi0.z * x.z + wi0.w * x.w;
            ai1[b] += wi1.x * x.x + wi1.y * x.y + wi1.z * x.z + wi1.w * x.w;
            ah0[b] += wh0.x * h.x + wh0.y * h.y + wh0.z * h.z + wh0.w * h.w;
            ah1[b] += wh1.x * h.x + wh1.y * h.y + wh1.z * h.z + wh1.w * h.w;
        }
    }

    #pragma unroll
    for (int b = 0; b < B; b++) {
        #pragma unroll
        for (int o = 16; o; o >>= 1) {
            ai0[b] += __shfl_xor_sync(0xffffffffu, ai0[b], o);
            ai1[b] += __shfl_xor_sync(0xffffffffu, ai1[b], o);
            ah0[b] += __shfl_xor_sync(0xffffffffu, ah0[b], o);
            ah1[b] += __shfl_xor_sync(0xffffffffu, ah1[b], o);
        }
    }

    if (lane == 0) {
        float bi0 = b_ih[j0], bi1 = b_ih[j0 + 1];
        float bh0 = b_hh[j0], bh1 = b_hh[j0 + 1];
        #pragma unroll
        for (int b = 0; b < B; b++) {
            g_gi[b * 3 * H + j0]     = ai0[b] + bi0;
            g_gi[b * 3 * H + j0 + 1] = ai1[b] + bi1;
            g_gh[b * 3 * H + j0]     = ah0[b] + bh0;
            g_gh[b * 3 * H + j0 + 1] = ah1[b] + bh1;
        }
    }
}

// ---------------------------------------------------------------------------
// K3: GRU cell gate math -> h1 [B,H]
// ---------------------------------------------------------------------------
__global__ void k3_gru() {
    int i = blockIdx.x * blockDim.x + threadIdx.x;
    int b = i >> 10;
    int h = i & (H - 1);
    int base = b * 3 * H + h;
    float ir = g_gi[base], iz = g_gi[base + H], in_ = g_gi[base + 2 * H];
    float hr = g_gh[base], hz = g_gh[base + H], hn  = g_gh[base + 2 * H];
    float r = 1.f / (1.f + expf(-(ir + hr)));
    float z = 1.f / (1.f + expf(-(iz + hz)));
    float n = tanhf(in_ + r * hn);
    g_h1[i] = (1.f - z) * n + z * g_h0[i];
}

// ---------------------------------------------------------------------------
// K4: logits[b,v] = h1[b,:] . proj_w[v,:] + proj_b[v]
// Batch-packed f32x2 (round 7) + cp.async double-buffered staging of proj_w:
// each warp's 4 rows x 512B iter-chunk lands in a private smem buffer; lane l
// copies and later reads float4 #l (self-written -> no syncwarp). Depth-2
// pipeline hides the DRAM/L2 latency that bounded round 7 (issue=42%).
// smem: 64KB hs + 32KB pf = 96KB -> still 2 CTAs/SM.
// ---------------------------------------------------------------------------
__global__ __launch_bounds__(256, 2)
void k4_proj(const float* __restrict__ proj_w,
             const float* __restrict__ proj_b) {
    extern __shared__ char smem_raw[];
    u64*  hs = (u64*)smem_raw;                    // 64KB, swizzled
    char* pf = smem_raw + 65536;                  // 32KB: [warp][buf][row][lane*16]

    for (int i = threadIdx.x; i < BP * H; i += 256) {
        int bp = i >> 10;
        int k  = i & (H - 1);
        unsigned lo = __float_as_uint(g_h1[(2 * bp) * H + k]);
        unsigned hi = __float_as_uint(g_h1[(2 * bp + 1) * H + k]);
        hs[swz(i)] = ((u64)hi << 32) | (u64)lo;
    }
    __syncthreads();

    int warp = threadIdx.x >> 5;
    int lane = threadIdx.x & 31;
    int v0 = (blockIdx.x * 8 + warp) * 4;
    if (v0 >= V) return;

    int r1 = min(v0 + 1, V - 1);
    int r2 = min(v0 + 2, V - 1);
    int r3 = min(v0 + 3, V - 1);
    const char* w0 = (const char*)(proj_w + (size_t)v0 * H);
    const char* w1 = (const char*)(proj_w + (size_t)r1 * H);
    const char* w2 = (const char*)(proj_w + (size_t)r2 * H);
    const char* w3 = (const char*)(proj_w + (size_t)r3 * H);

    // this warp's staging region (generic + .shared address forms)
    char* pfw = pf + warp * 4096 + lane * 16;
    unsigned pfw_s = (unsigned)__cvta_generic_to_shared(pfw);

    u64 a0[BP], a1[BP], a2[BP], a3[BP];
    #pragma unroll
    for (int bp = 0; bp < BP; bp++) { a0[bp] = a1[bp] = a2[bp] = a3[bp] = 0ull; }

    // prologue: stage iters 0 and 1
    {
        int off = lane * 16;
        cpasync16(pfw_s + 0 * 2048 + 0 * 512, w0 + off);
        cpasync16(pfw_s + 0 * 2048 + 1 * 512, w1 + off);
        cpasync16(pfw_s + 0 * 2048 + 2 * 512, w2 + off);
        cpasync16(pfw_s + 0 * 2048 + 3 * 512, w3 + off);
        cpcommit();
        cpasync16(pfw_s + 1 * 2048 + 0 * 512, w0 + 512 + off);
        cpasync16(pfw_s + 1 * 2048 + 1 * 512, w1 + 512 + off);
        cpasync16(pfw_s + 1 * 2048 + 2 * 512, w2 + 512 + off);
        cpasync16(pfw_s + 1 * 2048 + 3 * 512, w3 + 512 + off);
        cpcommit();
    }

    #pragma unroll
    for (int i = 0; i < 8; i++) {
        const int buf = i & 1;
        if (i < 6) cpwait<1>(); else cpwait<0>();

        // read this iter's staged proj_w (each lane reads its own 16B per row)
        const char* pb = pf + warp * 4096 + buf * 2048 + lane * 16;
        float4 p0 = *(const float4*)(pb + 0 * 512);
        float4 p1 = *(const float4*)(pb + 1 * 512);
        float4 p2 = *(const float4*)(pb + 2 * 512);
        float4 p3 = *(const float4*)(pb + 3 * 512);
        u64 q0x = dup2(p0.x), q0y = dup2(p0.y), q0z = dup2(p0.z), q0w = dup2(p0.w);
        u64 q1x = dup2(p1.x), q1y = dup2(p1.y), q1z = dup2(p1.z), q1w = dup2(p1.w);
        u64 q2x = dup2(p2.x), q2y = dup2(p2.y), q2z = dup2(p2.z), q2w = dup2(p2.w);
        u64 q3x = dup2(p3.x), q3y = dup2(p3.y), q3z = dup2(p3.z), q3w = dup2(p3.w);

        // refill the just-consumed buffer with iter i+2 (dup2 issue already
        // forced the pf LDS to complete -> no hazard)
        if (i < 6) {
            int off = (i + 2) * 512 + lane * 16;
            unsigned d = pfw_s + buf * 2048;
            cpasync16(d + 0 * 512, w0 + off);
            cpasync16(d + 1 * 512, w1 + off);
            cpasync16(d + 2 * 512, w2 + off);
            cpasync16(d + 3 * 512, w3 + off);
            cpcommit();
        }

        int kq = i * 32 + lane;                  // float4 index into the row
        #pragma unroll
        for (int bp = 0; bp < BP; bp++) {
            int idx = bp * 1024 + kq * 4;              // u64 index of k0
            int f   = ((idx >> 4) & 1) << 1;           // same for idx..idx+3
            ulonglong2 xa = *(const ulonglong2*)(hs + (idx ^ f));        // k0,k1
            ulonglong2 xb = *(const ulonglong2*)(hs + ((idx + 2) ^ f));  // k2,k3
            ffma2(a0[bp], q0x, xa.x); ffma2(a0[bp], q0y, xa.y);
            ffma2(a0[bp], q0z, xb.x); ffma2(a0[bp], q0w, xb.y);
            ffma2(a1[bp], q1x, xa.x); ffma2(a1[bp], q1y, xa.y);
            ffma2(a1[bp], q1z, xb.x); ffma2(a1[bp], q1w, xb.y);
            ffma2(a2[bp], q2x, xa.x); ffma2(a2[bp], q2y, xa.y);
            ffma2(a2[bp], q2z, xb.x); ffma2(a2[bp], q2w, xb.y);
            ffma2(a3[bp], q3x, xa.x); ffma2(a3[bp], q3y, xa.y);
            ffma2(a3[bp], q3z, xb.x); ffma2(a3[bp], q3w, xb.y);
        }
    }

    float pb0 = proj_b[v0];
    float pb1 = proj_b[r1];
    float pb2 = proj_b[r2];
    float pb3 = proj_b[r3];

    #pragma unroll
    for (int bp = 0; bp < BP; bp++) {
        float s0a = lo2(a0[bp]), s0b = hi2(a0[bp]);
        float s1a = lo2(a1[bp]), s1b = hi2(a1[bp]);
        float s2a = lo2(a2[bp]), s2b = hi2(a2[bp]);
        float s3a = lo2(a3[bp]), s3b = hi2(a3[bp]);
        #pragma unroll
        for (int o = 16; o; o >>= 1) {
            s0a += __shfl_xor_sync(0xffffffffu, s0a, o);
            s0b += __shfl_xor_sync(0xffffffffu, s0b, o);
            s1a += __shfl_xor_sync(0xffffffffu, s1a, o);
            s1b += __shfl_xor_sync(0xffffffffu, s1b, o);
            s2a += __shfl_xor_sync(0xffffffffu, s2a, o);
            s2b += __shfl_xor_sync(0xffffffffu, s2b, o);
            s3a += __shfl_xor_sync(0xffffffffu, s3a, o);
            s3b += __shfl_xor_sync(0xffffffffu, s3b, o);
        }
        if (lane == 0) {
            float* lga = g_logits + (size_t)(2 * bp) * V;
            float* lgb = g_logits + (size_t)(2 * bp + 1) * V;
            lga[v0] = s0a + pb0;  lgb[v0] = s0b + pb0;
            if (v0 + 1 < V) { lga[v0 + 1] = s1a + pb1;  lgb[v0 + 1] = s1b + pb1; }
            if (v0 + 2 < V) { lga[v0 + 2] = s2a + pb2;  lgb[v0 + 2] = s2b + pb2; }
            if (v0 + 3 < V) { lga[v0 + 3] = s3a + pb3;  lgb[v0 + 3] = s3b + pb3; }
        }
    }
}

// ---------------------------------------------------------------------------
// K5: per-batch max and log-sum-exp over V (logits hot in L2)
// ---------------------------------------------------------------------------
__global__ void k5_lse() {
    int b = blockIdx.x;
    __shared__ float red[256];
    const float* lg = g_logits + (size_t)b * V;

    float m = -1e30f;
    for (int v = threadIdx.x; v < V; v += 256) m = fmaxf(m, lg[v]);
    red[threadIdx.x] = m;
    __syncthreads();
    for (int s = 128; s; s >>= 1) {
        if (threadIdx.x < s) red[threadIdx.x] = fmaxf(red[threadIdx.x], red[threadIdx.x + s]);
        __syncthreads();
    }
    m = red[0];
    __syncthreads();

    float sum = 0.f;
    for (int v = threadIdx.x; v < V; v += 256) sum += expf(lg[v] - m);
    red[threadIdx.x] = sum;
    __syncthreads();
    for (int s = 128; s; s >>= 1) {
        if (threadIdx.x < s) red[threadIdx.x] += red[threadIdx.x + s];
        __syncthreads();
    }
    if (threadIdx.x == 0) { g_m[b] = m; g_l[b] = logf(red[0]); }
}

// ---------------------------------------------------------------------------
// K6: out[b,t,v] = logits[b,v] - m[b] - lse[b]  broadcast over t (127)
// ---------------------------------------------------------------------------
__global__ void k6_out(float* __restrict__ out) {
    int v = blockIdx.x * blockDim.x + threadIdx.x;
    int b = blockIdx.y;
    if (v >= V) return;
    float val = g_logits[(size_t)b * V + v] - g_m[b] - g_l[b];
    float* o = out + (size_t)b * T * V + v;
    #pragma unroll 8
    for (int t = 0; t < T; t++) o[(size_t)t * V] = val;
}

// ---------------------------------------------------------------------------
extern "C" void kernel_launch(void* const* d_in, const int* in_sizes, int n_in,
                              void* d_out, int out_size) {
    const int*   input    = (const int*)d_in[0];
    const float* hidden   = (const float*)d_in[1];
    const float* emb      = (const float*)d_in[2];
    const float* bridge_w = (const float*)d_in[3];
    const float* bridge_b = (const float*)d_in[4];
    const float* w_ih     = (const float*)d_in[5];
    const float* w_hh     = (const float*)d_in[6];
    const float* b_ih     = (const float*)d_in[7];
    const float* b_hh     = (const float*)d_in[8];
    const float* proj_w   = (const float*)d_in[9];
    const float* proj_b   = (const float*)d_in[10];
    float* out = (float*)d_out;

    const int k4_smem = 65536 + 32768;   // hs + pf
    cudaFuncSetAttribute(k4_proj, cudaFuncAttributeMaxDynamicSharedMemorySize,
                         k4_smem);

    // k4 is launch #4 -> lands in the ncu-profiled slot
    k1_embed_bridge<<<256, 256>>>(input, hidden, emb, bridge_w, bridge_b);
    k2_gates_mm<<<192, 256>>>(w_ih, w_hh, b_ih, b_hh);
    k3_gru<<<(B * H) / 256, 256>>>();
    int blocks4 = (V + 31) / 32;   // 8 warps x 4 rows per block
    k4_proj<<<blocks4, 256, k4_smem>>>(proj_w, proj_b);
    k5_lse<<<B, 256>>>();
    dim3 g6((V + 255) / 256, B);
    k6_out<<<g6, 256>>>(out);
}

// round 9
// speedup vs baseline: 1.5633x; 1.0645x over previous
#include <cuda_runtime.h>
#include <math.h>

#define B 16
#define L 128
#define H 1024
#define V 50257
#define T (L-1)
#define BP (B/2)
#define NPAIR 25128          // floor((V-1)/2): pairs cover v in [0,50255]/[1,50256]

typedef unsigned long long u64;

// ---- scratch (no allocations allowed) ----
__device__ float g_x0[B * H];
__device__ float g_h0[B * H];
__device__ float g_gi[B * 3 * H];
__device__ float g_gh[B * 3 * H];
__device__ float g_h1[B * H];
__device__ float g_logits[(size_t)B * V];
__device__ float g_m[B];
__device__ float g_l[B];

// packed f32x2 FMA: d = a*b + d (2 MACs / SASS FFMA2)
__device__ __forceinline__ void ffma2(u64 &d, u64 a, u64 b) {
    asm("fma.rn.f32x2 %0, %1, %2, %0;" : "+l"(d) : "l"(a), "l"(b));
}
__device__ __forceinline__ u64 dup2(float f) {
    u64 r;
    asm("mov.b64 %0, {%1, %1};" : "=l"(r) : "f"(f));
    return r;
}
__device__ __forceinline__ float lo2(u64 a) { return __uint_as_float((unsigned)a); }
__device__ __forceinline__ float hi2(u64 a) { return __uint_as_float((unsigned)(a >> 32)); }

// XOR swizzle on u64 index: flips the 16B-granule bit on alternating 128B lines
__device__ __forceinline__ int swz(int i) { return i ^ (((i >> 4) & 1) << 1); }

// cp.async 16B, L2-only path (streaming)
__device__ __forceinline__ void cpasync16(unsigned dst, const void* src) {
    asm volatile("cp.async.cg.shared.global [%0], [%1], 16;" :: "r"(dst), "l"(src) : "memory");
}
__device__ __forceinline__ void cpcommit() {
    asm volatile("cp.async.commit_group;" ::: "memory");
}
template <int N>
__device__ __forceinline__ void cpwait() {
    asm volatile("cp.async.wait_group %0;" :: "n"(N) : "memory");
}

// ---------------------------------------------------------------------------
// K1: x0 = relu(emb[input[:,0]]);  h0[b,h] = sum_l hidden[b,l,h]*bw[l] + bb
// 4 threads per (b,h), each reducing 32 l-values; smem combine. grid=256.
// ---------------------------------------------------------------------------
__global__ void k1_embed_bridge(const int* __restrict__ input,
                                const float* __restrict__ hidden,
                                const float* __restrict__ emb,
                                const float* __restrict__ bridge_w,
                                const float* __restrict__ bridge_b) {
    __shared__ float bw[L];
    __shared__ float part[4][64];
    int tid = threadIdx.x;
    if (tid < L) bw[tid] = bridge_w[tid];
    __syncthreads();

    int slot = tid & 63;
    int lc   = tid >> 6;
    int i = blockIdx.x * 64 + slot;
    int b = i >> 10;
    int h = i & (H - 1);

    const float* hp = hidden + (size_t)b * L * H + (size_t)(lc * 32) * H + h;
    float a0 = 0.f, a1 = 0.f, a2 = 0.f, a3 = 0.f;
    #pragma unroll
    for (int l = 0; l < 32; l += 4) {
        a0 += hp[(l + 0) * H] * bw[lc * 32 + l + 0];
        a1 += hp[(l + 1) * H] * bw[lc * 32 + l + 1];
        a2 += hp[(l + 2) * H] * bw[lc * 32 + l + 2];
        a3 += hp[(l + 3) * H] * bw[lc * 32 + l + 3];
    }
    part[lc][slot] = (a0 + a1) + (a2 + a3);
    __syncthreads();

    if (lc == 0) {
        int tok = input[b * L];
        g_x0[i] = fmaxf(emb[(size_t)tok * H + h], 0.0f);
        g_h0[i] = (part[0][slot] + part[1][slot]) +
                  (part[2][slot] + part[3][slot]) + bridge_b[0];
    }
}

// ---------------------------------------------------------------------------
// K2: gi = x0 @ w_ih^T + b_ih ; gh = h0 @ w_hh^T + b_hh   (both [B, 3H])
// ---------------------------------------------------------------------------
__global__ void k2_gates_mm(const float* __restrict__ w_ih,
                            const float* __restrict__ w_hh,
                            const float* __restrict__ b_ih,
                            const float* __restrict__ b_hh) {
    int warp = threadIdx.x >> 5;
    int lane = threadIdx.x & 31;
    int j0 = (blockIdx.x * 8 + warp) * 2;

    float ai0[B], ai1[B], ah0[B], ah1[B];
    #pragma unroll
    for (int b = 0; b < B; b++) { ai0[b] = ai1[b] = ah0[b] = ah1[b] = 0.f; }

    for (int i = 0; i < 8; i++) {
        int k = i * 128 + lane * 4;
        float4 wi0 = *(const float4*)(w_ih + (size_t)(j0 + 0) * H + k);
        float4 wi1 = *(const float4*)(w_ih + (size_t)(j0 + 1) * H + k);
        float4 wh0 = *(const float4*)(w_hh + (size_t)(j0 + 0) * H + k);
        float4 wh1 = *(const float4*)(w_hh + (size_t)(j0 + 1) * H + k);
        #pragma unroll
        for (int b = 0; b < B; b++) {
            float4 x = *(const float4*)(g_x0 + b * H + k);
            float4 h = *(const float4*)(g_h0 + b * H + k);
            ai0[b] += wi0.x * x.x + wi0.y * x.y + wi0.z * x.z + wi0.w * x.w;
            ai1[b] += wi1.x * x.x + wi1.y * x.y + wi1.z * x.z + wi1.w * x.w;
            ah0[b] += wh0.x * h.x + wh0.y * h.y + wh0.z * h.z + wh0.w * h.w;
            ah1[b] += wh1.x * h.x + wh1.y * h.y + wh1.z * h.z + wh1.w * h.w;
        }
    }

    #pragma unroll
    for (int b = 0; b < B; b++) {
        #pragma unroll
        for (int o = 16; o; o >>= 1) {
            ai0[b] += __shfl_xor_sync(0xffffffffu, ai0[b], o);
            ai1[b] += __shfl_xor_sync(0xffffffffu, ai1[b], o);
            ah0[b] += __shfl_xor_sync(0xffffffffu, ah0[b], o);
            ah1[b] += __shfl_xor_sync(0xffffffffu, ah1[b], o);
        }
    }

    if (lane == 0) {
        float bi0 = b_ih[j0], bi1 = b_ih[j0 + 1];
        float bh0 = b_hh[j0], bh1 = b_hh[j0 + 1];
        #pragma unroll
        for (int b = 0; b < B; b++) {
            g_gi[b * 3 * H + j0]     = ai0[b] + bi0;
            g_gi[b * 3 * H + j0 + 1] = ai1[b] + bi1;
            g_gh[b * 3 * H + j0]     = ah0[b] + bh0;
            g_gh[b * 3 * H + j0 + 1] = ah1[b] + bh1;
        }
    }
}

// ---------------------------------------------------------------------------
// K3: GRU cell gate math -> h1 [B,H]
// ---------------------------------------------------------------------------
__global__ void k3_gru() {
    int i = blockIdx.x * blockDim.x + threadIdx.x;
    int b = i >> 10;
    int h = i & (H - 1);
    int base = b * 3 * H + h;
    float ir = g_gi[base], iz = g_gi[base + H], in_ = g_gi[base + 2 * H];
    float hr = g_gh[base], hz = g_gh[base + H], hn  = g_gh[base + 2 * H];
    float r = 1.f / (1.f + expf(-(ir + hr)));
    float z = 1.f / (1.f + expf(-(iz + hz)));
    float n = tanhf(in_ + r * hn);
    g_h1[i] = (1.f - z) * n + z * g_h0[i];
}

// ---------------------------------------------------------------------------
// K4: logits[b,v] = h1[b,:] . proj_w[v,:] + proj_b[v]
// Batch-packed f32x2 + swizzled smem h1 + cp.async double-buffered proj_w.
// (round-8 committed version, unchanged)
// ---------------------------------------------------------------------------
__global__ __launch_bounds__(256, 2)
void k4_proj(const float* __restrict__ proj_w,
             const float* __restrict__ proj_b) {
    extern __shared__ char smem_raw[];
    u64*  hs = (u64*)smem_raw;                    // 64KB, swizzled
    char* pf = smem_raw + 65536;                  // 32KB staging

    for (int i = threadIdx.x; i < BP * H; i += 256) {
        int bp = i >> 10;
        int k  = i & (H - 1);
        unsigned lo = __float_as_uint(g_h1[(2 * bp) * H + k]);
        unsigned hi = __float_as_uint(g_h1[(2 * bp + 1) * H + k]);
        hs[swz(i)] = ((u64)hi << 32) | (u64)lo;
    }
    __syncthreads();

    int warp = threadIdx.x >> 5;
    int lane = threadIdx.x & 31;
    int v0 = (blockIdx.x * 8 + warp) * 4;
    if (v0 >= V) return;

    int r1 = min(v0 + 1, V - 1);
    int r2 = min(v0 + 2, V - 1);
    int r3 = min(v0 + 3, V - 1);
    const char* w0 = (const char*)(proj_w + (size_t)v0 * H);
    const char* w1 = (const char*)(proj_w + (size_t)r1 * H);
    const char* w2 = (const char*)(proj_w + (size_t)r2 * H);
    const char* w3 = (const char*)(proj_w + (size_t)r3 * H);

    char* pfw = pf + warp * 4096 + lane * 16;
    unsigned pfw_s = (unsigned)__cvta_generic_to_shared(pfw);

    u64 a0[BP], a1[BP], a2[BP], a3[BP];
    #pragma unroll
    for (int bp = 0; bp < BP; bp++) { a0[bp] = a1[bp] = a2[bp] = a3[bp] = 0ull; }

    {
        int off = lane * 16;
        cpasync16(pfw_s + 0 * 2048 + 0 * 512, w0 + off);
        cpasync16(pfw_s + 0 * 2048 + 1 * 512, w1 + off);
        cpasync16(pfw_s + 0 * 2048 + 2 * 512, w2 + off);
        cpasync16(pfw_s + 0 * 2048 + 3 * 512, w3 + off);
        cpcommit();
        cpasync16(pfw_s + 1 * 2048 + 0 * 512, w0 + 512 + off);
        cpasync16(pfw_s + 1 * 2048 + 1 * 512, w1 + 512 + off);
        cpasync16(pfw_s + 1 * 2048 + 2 * 512, w2 + 512 + off);
        cpasync16(pfw_s + 1 * 2048 + 3 * 512, w3 + 512 + off);
        cpcommit();
    }

    #pragma unroll
    for (int i = 0; i < 8; i++) {
        const int buf = i & 1;
        if (i < 6) cpwait<1>(); else cpwait<0>();

        const char* pb = pf + warp * 4096 + buf * 2048 + lane * 16;
        float4 p0 = *(const float4*)(pb + 0 * 512);
        float4 p1 = *(const float4*)(pb + 1 * 512);
        float4 p2 = *(const float4*)(pb + 2 * 512);
        float4 p3 = *(const float4*)(pb + 3 * 512);
        u64 q0x = dup2(p0.x), q0y = dup2(p0.y), q0z = dup2(p0.z), q0w = dup2(p0.w);
        u64 q1x = dup2(p1.x), q1y = dup2(p1.y), q1z = dup2(p1.z), q1w = dup2(p1.w);
        u64 q2x = dup2(p2.x), q2y = dup2(p2.y), q2z = dup2(p2.z), q2w = dup2(p2.w);
        u64 q3x = dup2(p3.x), q3y = dup2(p3.y), q3z = dup2(p3.z), q3w = dup2(p3.w);

        if (i < 6) {
            int off = (i + 2) * 512 + lane * 16;
            unsigned d = pfw_s + buf * 2048;
            cpasync16(d + 0 * 512, w0 + off);
            cpasync16(d + 1 * 512, w1 + off);
            cpasync16(d + 2 * 512, w2 + off);
            cpasync16(d + 3 * 512, w3 + off);
            cpcommit();
        }

        int kq = i * 32 + lane;
        #pragma unroll
        for (int bp = 0; bp < BP; bp++) {
            int idx = bp * 1024 + kq * 4;
            int f   = ((idx >> 4) & 1) << 1;
            ulonglong2 xa = *(const ulonglong2*)(hs + (idx ^ f));
            ulonglong2 xb = *(const ulonglong2*)(hs + ((idx + 2) ^ f));
            ffma2(a0[bp], q0x, xa.x); ffma2(a0[bp], q0y, xa.y);
            ffma2(a0[bp], q0z, xb.x); ffma2(a0[bp], q0w, xb.y);
            ffma2(a1[bp], q1x, xa.x); ffma2(a1[bp], q1y, xa.y);
            ffma2(a1[bp], q1z, xb.x); ffma2(a1[bp], q1w, xb.y);
            ffma2(a2[bp], q2x, xa.x); ffma2(a2[bp], q2y, xa.y);
            ffma2(a2[bp], q2z, xb.x); ffma2(a2[bp], q2w, xb.y);
            ffma2(a3[bp], q3x, xa.x); ffma2(a3[bp], q3y, xa.y);
            ffma2(a3[bp], q3z, xb.x); ffma2(a3[bp], q3w, xb.y);
        }
    }

    float pb0 = proj_b[v0];
    float pb1 = proj_b[r1];
    float pb2 = proj_b[r2];
    float pb3 = proj_b[r3];

    #pragma unroll
    for (int bp = 0; bp < BP; bp++) {
        float s0a = lo2(a0[bp]), s0b = hi2(a0[bp]);
        float s1a = lo2(a1[bp]), s1b = hi2(a1[bp]);
        float s2a = lo2(a2[bp]), s2b = hi2(a2[bp]);
        float s3a = lo2(a3[bp]), s3b = hi2(a3[bp]);
        #pragma unroll
        for (int o = 16; o; o >>= 1) {
            s0a += __shfl_xor_sync(0xffffffffu, s0a, o);
            s0b += __shfl_xor_sync(0xffffffffu, s0b, o);
            s1a += __shfl_xor_sync(0xffffffffu, s1a, o);
            s1b += __shfl_xor_sync(0xffffffffu, s1b, o);
            s2a += __shfl_xor_sync(0xffffffffu, s2a, o);
            s2b += __shfl_xor_sync(0xffffffffu, s2b, o);
            s3a += __shfl_xor_sync(0xffffffffu, s3a, o);
            s3b += __shfl_xor_sync(0xffffffffu, s3b, o);
        }
        if (lane == 0) {
            float* lga = g_logits + (size_t)(2 * bp) * V;
            float* lgb = g_logits + (size_t)(2 * bp + 1) * V;
            lga[v0] = s0a + pb0;  lgb[v0] = s0b + pb0;
            if (v0 + 1 < V) { lga[v0 + 1] = s1a + pb1;  lgb[v0 + 1] = s1b + pb1; }
            if (v0 + 2 < V) { lga[v0 + 2] = s2a + pb2;  lgb[v0 + 2] = s2b + pb2; }
            if (v0 + 3 < V) { lga[v0 + 3] = s3a + pb3;  lgb[v0 + 3] = s3b + pb3; }
        }
    }
}

// ---------------------------------------------------------------------------
// K5: per-batch max and log-sum-exp over V (logits hot in L2)
// ---------------------------------------------------------------------------
__global__ void k5_lse() {
    int b = blockIdx.x;
    __shared__ float red[256];
    const float* lg = g_logits + (size_t)b * V;

    float m = -1e30f;
    for (int v = threadIdx.x; v < V; v += 256) m = fmaxf(m, lg[v]);
    red[threadIdx.x] = m;
    __syncthreads();
    for (int s = 128; s; s >>= 1) {
        if (threadIdx.x < s) red[threadIdx.x] = fmaxf(red[threadIdx.x], red[threadIdx.x + s]);
        __syncthreads();
    }
    m = red[0];
    __syncthreads();

    float sum = 0.f;
    for (int v = threadIdx.x; v < V; v += 256) sum += expf(lg[v] - m);
    red[threadIdx.x] = sum;
    __syncthreads();
    for (int s = 128; s; s >>= 1) {
        if (threadIdx.x < s) red[threadIdx.x] += red[threadIdx.x + s];
        __syncthreads();
    }
    if (threadIdx.x == 0) { g_m[b] = m; g_l[b] = logf(red[0]); }
}

// ---------------------------------------------------------------------------
// K6: out[b,t,v] = logits[b,v] - m[b] - lse[b], broadcast over t, with
// STG.64 pairing. Row base parity = (b+t)&1 (V and T odd), so:
//   (b+t) even: store pairs (2j, 2j+1)   -> 8B aligned
//   (b+t) odd : store pairs (2j+1, 2j+2) -> 8B aligned
// Each thread owns pair index j, precomputes both pair variants from 3
// logits, and runs two stride-2 t loops. Thread j==NPAIR covers the
// leftover singles (v=V-1 for even parity, v=0 for odd parity).
// Halves STG instruction count (k6 was STG.32-issue-bound).
// ---------------------------------------------------------------------------
__global__ void k6_out(float* __restrict__ out) {
    int j = blockIdx.x * blockDim.x + threadIdx.x;
    int b = blockIdx.y;
    if (j > NPAIR) return;
    float sub = g_m[b] + g_l[b];
    const float* lg = g_logits + (size_t)b * V;
    float* ob = out + (size_t)b * T * V;
    int tA = b & 1;            // t values with (b+t) even start here

    if (j < NPAIR) {
        float l0 = lg[2 * j] - sub;
        float l1 = lg[2 * j + 1] - sub;
        float l2 = (2 * j + 2 < V) ? (lg[2 * j + 2] - sub) : 0.f;
        float2 pA = make_float2(l0, l1);   // at v = 2j   ((b+t) even)
        float2 pB = make_float2(l1, l2);   // at v = 2j+1 ((b+t) odd)
        #pragma unroll 4
        for (int t = tA; t < T; t += 2)
            *(float2*)(ob + (size_t)t * V + 2 * j) = pA;
        #pragma unroll 4
        for (int t = tA ^ 1; t < T; t += 2)
            *(float2*)(ob + (size_t)t * V + 2 * j + 1) = pB;
    } else {                   // j == NPAIR: singles
        float lN = lg[V - 1] - sub;
        float l0 = lg[0] - sub;
        for (int t = tA; t < T; t += 2)
            ob[(size_t)t * V + V - 1] = lN;     // (b+t) even: v=V-1 uncovered
        for (int t = tA ^ 1; t < T; t += 2)
            ob[(size_t)t * V] = l0;             // (b+t) odd: v=0 uncovered
    }
}

// ---------------------------------------------------------------------------
extern "C" void kernel_launch(void* const* d_in, const int* in_sizes, int n_in,
                              void* d_out, int out_size) {
    const int*   input    = (const int*)d_in[0];
    const float* hidden   = (const float*)d_in[1];
    const float* emb      = (const float*)d_in[2];
    const float* bridge_w = (const float*)d_in[3];
    const float* bridge_b = (const float*)d_in[4];
    const float* w_ih     = (const float*)d_in[5];
    const float* w_hh     = (const float*)d_in[6];
    const float* b_ih     = (const float*)d_in[7];
    const float* b_hh     = (const float*)d_in[8];
    const float* proj_w   = (const float*)d_in[9];
    const float* proj_b   = (const float*)d_in[10];
    float* out = (float*)d_out;

    const int k4_smem = 65536 + 32768;
    cudaFuncSetAttribute(k4_proj, cudaFuncAttributeMaxDynamicSharedMemorySize,
                         k4_smem);

    // k4 is launch #4 -> lands in the ncu-profiled slot
    k1_embed_bridge<<<256, 256>>>(input, hidden, emb, bridge_w, bridge_b);
    k2_gates_mm<<<192, 256>>>(w_ih, w_hh, b_ih, b_hh);
    k3_gru<<<(B * H) / 256, 256>>>();
    int blocks4 = (V + 31) / 32;
    k4_proj<<<blocks4, 256, k4_smem>>>(proj_w, proj_b);
    k5_lse<<<B, 256>>>();
    dim3 g6((NPAIR + 1 + 255) / 256, B);
    k6_out<<<g6, 256>>>(out);
}